// round 7
// baseline (speedup 1.0000x reference)
#include <cuda_runtime.h>

#define EPSF     1e-9f
#define BCE_EPSF 1e-7f
#define NGT      150
#define NGT_PAD  152
#define NBLOCKS  504    // 512 anchors per block (256 threads x 2 anchors)

__device__ double       g_acc;
__device__ unsigned int g_count;

struct AnchorState {
    float brx, bry, ntlx, ntly;   // anchor corners, tl negated
    float giou, fb, gcf, thresh;  // thresh = area1 * (2/3)
};

static __device__ __forceinline__ AnchorState prep_anchor(const float* __restrict__ p,
                                                          const float* __restrict__ q) {
    float ox = p[0], oy = p[1], ow = p[2], oh = p[3], oc = p[4];
    float gx = q[0], gy = q[1], gw = q[2], gh = q[3], gcf = q[4];

    float tl1x = ox - 0.5f * ow, tl1y = oy - 0.5f * oh;
    float br1x = ox + 0.5f * ow, br1y = oy + 0.5f * oh;
    float area1 = ow * oh;

    // ---- DIoU vs paired gt ----
    float tl2x = gx - 0.5f * gw, tl2y = gy - 0.5f * gh;
    float br2x = gx + 0.5f * gw, br2y = gy + 0.5f * gh;
    float area2 = gw * gh;

    float iwx = fmaxf(fminf(br1x, br2x) - fmaxf(tl1x, tl2x), 0.0f);
    float iwy = fmaxf(fminf(br1y, br2y) - fmaxf(tl1y, tl2y), 0.0f);
    float inter = iwx * iwy;
    float iou = inter / (area1 + area2 - inter + EPSF);

    float dx = ox - gx, dy = oy - gy;
    float cd2 = dx * dx + dy * dy;
    float ex = fmaxf(br1x, br2x) - fminf(tl1x, tl2x);
    float ey = fmaxf(br1y, br2y) - fminf(tl1y, tl2y);
    float diou = iou - cd2 / (ex * ex + ey * ey + EPSF);

    // ---- focal BCE pieces (background-independent) ----
    float pcl = fminf(fmaxf(oc, BCE_EPSF), 1.0f - BCE_EPSF);
    float bce = -(gcf * __logf(pcl) + (1.0f - gcf) * __logf(1.0f - pcl));
    float d = gcf - oc;
    float focal = fabsf(gcf - 0.75f) * (d * d);

    AnchorState s;
    s.brx  = br1x;  s.bry  = br1y;
    s.ntlx = -tl1x; s.ntly = -tl1y;
    s.giou = gcf * (2.0f - area2 * (1.0f / (512.0f * 512.0f))) * (1.0f - diou);
    s.fb   = focal * bce;
    s.gcf  = gcf;
    s.thresh = area1 * (2.0f / 3.0f);
    return s;
}

__global__ void __launch_bounds__(256) fused_loss_kernel(
    const float* __restrict__ s_out, const float* __restrict__ m_out,
    const float* __restrict__ l_out,
    const float* __restrict__ s_gt,  const float* __restrict__ m_gt,
    const float* __restrict__ l_gt,
    const float* __restrict__ s_gc,  const float* __restrict__ m_gc,
    const float* __restrict__ l_gc,
    float* __restrict__ out, float inv_b)
{
    __shared__ float4 s_box[NGT_PAD];   // brx, bry, ntlx, ntly  (tl negated)
    __shared__ float  s_th2[NGT_PAD];   // -(area2+eps)*(2/3); sentinel -1e38 on pad
    __shared__ float  s_red[8];

    // ---- map block -> (scale, batch, local block of 512 anchors) ----
    // s: 12288 anchors = 24 blocks/batch -> blocks [0,384)
    // m:  3072 anchors =  6 blocks/batch -> blocks [384,480)
    // l:   768 anchors = 1.5 blocks/batch -> handled as 24 blocks over 16 batches:
    //      use 512-anchor blocks with batch = (r*512)/768 pattern — instead simpler:
    //      l has 768*16 = 12288 anchors total = 24 blocks, flat-indexed.
    const int bb = blockIdx.x;
    const float *out_t, *gt_t, *gc_base;
    int b, a0, apb;
    if (bb < 384) {             // s: 24 blocks/batch
        b = bb / 24; a0 = (bb - b * 24) * 512; apb = 12288;
        out_t = s_out; gt_t = s_gt; gc_base = s_gc;
    } else if (bb < 480) {      // m: 6 blocks/batch
        int r = bb - 384; b = r / 6; a0 = (r - b * 6) * 512; apb = 3072;
        out_t = m_out; gt_t = m_gt; gc_base = m_gc;
    } else {                    // l: 768 anchors/batch; 512-anchor block spans
        int r = bb - 480;       // 0..23 ; anchor range [r*512, r*512+512) flat
        int flat = r * 512;
        b = flat / 768; a0 = flat - b * 768; apb = 768;
        out_t = l_out; gt_t = l_gt; gc_base = l_gc;
        // NOTE: a0 in {0, 512, 256(next b)}; second anchor (a0+256..) may cross
        // into next batch — handled below by per-anchor batch math instead.
    }

    // For the l-scale, a 512-anchor block can straddle a batch boundary.
    // Compute per-anchor (batch, index) from flat indices to stay correct.
    int fa0, fa1;                 // flat anchor indices within this scale
    if (bb < 480) {
        fa0 = b * apb + a0 + threadIdx.x;
        fa1 = fa0 + 256;
    } else {
        int flat = (bb - 480) * 512 + threadIdx.x;
        fa0 = flat; fa1 = flat + 256;
    }
    const int b0 = fa0 / apb;     // batch of anchor 0 (uniform across block for s/m)
    const int b1 = fa1 / apb;     // batch of anchor 1

    // ---- stage gt boxes for batch b0 (s/m: b1==b0; l: may differ -> see below) ----
    // For l-scale blocks that straddle, both halves still need their own gt set.
    // Straddling happens only for l (3 of 24 blocks per 2-batch group). We stage
    // b0's boxes and, when b1 != b0, the second anchor falls back to recomputing
    // with b1's boxes staged in the second half-pass.
    // Simplification: stage gt for b0 and for b1 (equal when not straddling).
    const float* gc0 = gc_base + (size_t)b0 * NGT * 4;
    for (int n = threadIdx.x; n < NGT_PAD; n += 256) {
        if (n < NGT) {
            float x = gc0[n * 4 + 0], y = gc0[n * 4 + 1];
            float w = gc0[n * 4 + 2], h = gc0[n * 4 + 3];
            float hw = 0.5f * w, hh = 0.5f * h;
            s_box[n] = make_float4(x + hw, y + hh, hw - x, hh - y);
            s_th2[n] = -(w * h + EPSF) * (2.0f / 3.0f);
        } else {
            s_box[n] = make_float4(0.0f, 0.0f, 0.0f, 0.0f);
            s_th2[n] = -1.0e38f;
        }
    }
    __syncthreads();

    // ---- two anchors per thread ----
    const size_t e0 = (size_t)fa0 * 5;   // element offsets are flat over (b, anchors)
    const size_t e1 = (size_t)fa1 * 5;
    AnchorState A = prep_anchor(out_t + e0, gt_t + e0);
    AnchorState C = prep_anchor(out_t + e1, gt_t + e1);

    // ---- background gate for anchor A (batch b0, staged boxes) and C if b1==b0 --
    float mA = -3.0e38f, mC = -3.0e38f;
    const bool same_batch = (b1 == b0);
    #pragma unroll 4
    for (int n = 0; n < NGT_PAD; n++) {
        float4 bx = s_box[n];
        float th = s_th2[n];

        float wxA = fminf(A.brx, bx.x) + fminf(A.ntlx, bx.z);
        float wyA = fminf(A.bry, bx.y) + fminf(A.ntly, bx.w);
        float uA  = wxA + fabsf(wxA);
        mA = fmaxf(mA, fmaf(uA, wyA, th));

        float wxC = fminf(C.brx, bx.x) + fminf(C.ntlx, bx.z);
        float wyC = fminf(C.bry, bx.y) + fminf(C.ntly, bx.w);
        float uC  = wxC + fabsf(wxC);
        mC = fmaxf(mC, fmaf(uC, wyC, th));
    }

    // ---- rare straddle fixup (l-scale only): redo C against b1's gt from global --
    if (!same_batch) {
        mC = -3.0e38f;
        const float* gc1 = gc_base + (size_t)b1 * NGT * 4;
        for (int n = 0; n < NGT; n++) {
            float x = gc1[n * 4 + 0], y = gc1[n * 4 + 1];
            float w = gc1[n * 4 + 2], h = gc1[n * 4 + 3];
            float hw = 0.5f * w, hh = 0.5f * h;
            float wxC = fminf(C.brx, x + hw) + fminf(C.ntlx, hw - x);
            float wyC = fminf(C.bry, y + hh) + fminf(C.ntly, hh - y);
            float uC  = wxC + fabsf(wxC);
            mC = fmaxf(mC, fmaf(uC, wyC, -(w * h + EPSF) * (2.0f / 3.0f)));
        }
    }

    float bgA = (mA >= A.thresh) ? 0.0f : (1.0f - A.gcf);
    float bgC = (mC >= C.thresh) ? 0.0f : (1.0f - C.gcf);

    float loss = A.giou + A.fb * (A.gcf + bgA)
               + C.giou + C.fb * (C.gcf + bgC);

    // ---- block reduction (8 warps) ----
    #pragma unroll
    for (int off = 16; off > 0; off >>= 1)
        loss += __shfl_down_sync(0xffffffffu, loss, off);

    int wid = threadIdx.x >> 5, lid = threadIdx.x & 31;
    if (lid == 0) s_red[wid] = loss;
    __syncthreads();

    // ---- global accumulate; last block writes output and resets ----
    if (threadIdx.x == 0) {
        float t = 0.0f;
        #pragma unroll
        for (int i = 0; i < 8; i++) t += s_red[i];
        atomicAdd(&g_acc, (double)t);
        __threadfence();
        unsigned int old = atomicAdd(&g_count, 1u);
        if (old == NBLOCKS - 1) {
            double v = atomicAdd(&g_acc, 0.0);   // coherent read
            out[0] = (float)(v * (double)inv_b);
            g_acc = 0.0;                          // reset for next replay
            g_count = 0u;
            __threadfence();
        }
    }
}

extern "C" void kernel_launch(void* const* d_in, const int* in_sizes, int n_in,
                              void* d_out, int out_size)
{
    const float* s_out = (const float*)d_in[0];
    const float* m_out = (const float*)d_in[1];
    const float* l_out = (const float*)d_in[2];
    const float* s_gt  = (const float*)d_in[3];
    const float* m_gt  = (const float*)d_in[4];
    const float* l_gt  = (const float*)d_in[5];
    const float* s_gc  = (const float*)d_in[6];
    const float* m_gc  = (const float*)d_in[7];
    const float* l_gc  = (const float*)d_in[8];

    const int B = in_sizes[6] / (NGT * 4);   // 16

    fused_loss_kernel<<<NBLOCKS, 256>>>(s_out, m_out, l_out,
                                        s_gt, m_gt, l_gt,
                                        s_gc, m_gc, l_gc,
                                        (float*)d_out, 1.0f / (float)B);
}

// round 8
// speedup vs baseline: 1.3265x; 1.3265x over previous
#include <cuda_runtime.h>

#define EPSF     1e-9f
#define BCE_EPSF 1e-7f
#define NGT      150
#define NGT_PAD  152
#define NBLOCKS  1008   // 768 (s) + 192 (m) + 48 (l) with 256 threads/block

__device__ double       g_acc;
__device__ unsigned int g_count;

__global__ void __launch_bounds__(256) fused_loss_kernel(
    const float* __restrict__ s_out, const float* __restrict__ m_out,
    const float* __restrict__ l_out,
    const float* __restrict__ s_gt,  const float* __restrict__ m_gt,
    const float* __restrict__ l_gt,
    const float* __restrict__ s_gc,  const float* __restrict__ m_gc,
    const float* __restrict__ l_gc,
    float* __restrict__ out, float inv_b)
{
    __shared__ float4 s_box[NGT_PAD];   // brx, bry, -tlx, -tly  (tl pre-negated)
    __shared__ float  s_th2[NGT_PAD];   // -(area2+eps)*(2/3); sentinel -1e38 on pad
    __shared__ float  s_red[8];

    // ---- map block -> (scale, batch, local block) ----
    const int bb = blockIdx.x;
    const float *out_t, *gt_t, *gc;
    int b, lb, apb;
    if (bb < 768) {             // s: 48 blocks/batch, 12288 anchors
        b = bb / 48; lb = bb - b * 48; apb = 12288;
        out_t = s_out; gt_t = s_gt; gc = s_gc;
    } else if (bb < 960) {      // m: 12 blocks/batch
        int r = bb - 768; b = r / 12; lb = r - b * 12; apb = 3072;
        out_t = m_out; gt_t = m_gt; gc = m_gc;
    } else {                    // l: 3 blocks/batch
        int r = bb - 960; b = r / 3; lb = r - b * 3; apb = 768;
        out_t = l_out; gt_t = l_gt; gc = l_gc;
    }

    // ---- stage gt boxes (tl negated, threshold pre-scaled by 2/3) ----
    gc += (size_t)b * NGT * 4;
    for (int n = threadIdx.x; n < NGT_PAD; n += 256) {
        if (n < NGT) {
            float x = gc[n * 4 + 0], y = gc[n * 4 + 1];
            float w = gc[n * 4 + 2], h = gc[n * 4 + 3];
            float hw = 0.5f * w, hh = 0.5f * h;
            s_box[n] = make_float4(x + hw, y + hh, hw - x, hh - y);
            s_th2[n] = -(w * h + EPSF) * (2.0f / 3.0f);
        } else {
            s_box[n] = make_float4(0.0f, 0.0f, 0.0f, 0.0f);
            s_th2[n] = -1.0e38f;    // sentinel: never exceeds threshold
        }
    }
    __syncthreads();

    const int a = lb * 256 + threadIdx.x;          // always < apb
    const size_t base = ((size_t)b * apb + a) * 5;
    const float* p = out_t + base;
    const float* q = gt_t  + base;
    float ox = p[0], oy = p[1], ow = p[2], oh = p[3], oc = p[4];
    float gx = q[0], gy = q[1], gw = q[2], gh = q[3], gcf = q[4];

    float tl1x = ox - 0.5f * ow, tl1y = oy - 0.5f * oh;
    float br1x = ox + 0.5f * ow, br1y = oy + 0.5f * oh;
    float ntl1x = -tl1x, ntl1y = -tl1y;
    float area1 = ow * oh;

    // ---- DIoU vs paired gt ----
    float tl2x = gx - 0.5f * gw, tl2y = gy - 0.5f * gh;
    float br2x = gx + 0.5f * gw, br2y = gy + 0.5f * gh;
    float area2 = gw * gh;

    float iwx = fmaxf(fminf(br1x, br2x) - fmaxf(tl1x, tl2x), 0.0f);
    float iwy = fmaxf(fminf(br1y, br2y) - fmaxf(tl1y, tl2y), 0.0f);
    float inter = iwx * iwy;
    float iou = inter / (area1 + area2 - inter + EPSF);

    float dx = ox - gx, dy = oy - gy;
    float cd2 = dx * dx + dy * dy;
    float ex = fmaxf(br1x, br2x) - fminf(tl1x, tl2x);
    float ey = fmaxf(br1y, br2y) - fminf(tl1y, tl2y);
    float diou = iou - cd2 / (ex * ex + ey * ey + EPSF);

    float giou_loss = gcf * (2.0f - area2 * (1.0f / (512.0f * 512.0f))) * (1.0f - diou);

    // ---- background gate: any(iou vs gt_coords >= 0.5)?
    // iou>=0.5 <=> 3*inter >= a1+a2+eps <=> (wx+|wx|)*wy >= (2/3)*(a1+a2+eps)
    float m0 = -3.0e38f, m1 = -3.0e38f, m2 = -3.0e38f, m3 = -3.0e38f;
    #pragma unroll 2
    for (int n = 0; n < NGT_PAD; n += 4) {
        float4 b0 = s_box[n];
        float wx0 = fminf(br1x, b0.x) + fminf(ntl1x, b0.z);
        float wy0 = fminf(br1y, b0.y) + fminf(ntl1y, b0.w);
        float u0  = wx0 + fabsf(wx0);
        m0 = fmaxf(m0, fmaf(u0, wy0, s_th2[n]));

        float4 b1 = s_box[n + 1];
        float wx1 = fminf(br1x, b1.x) + fminf(ntl1x, b1.z);
        float wy1 = fminf(br1y, b1.y) + fminf(ntl1y, b1.w);
        float u1  = wx1 + fabsf(wx1);
        m1 = fmaxf(m1, fmaf(u1, wy1, s_th2[n + 1]));

        float4 b2 = s_box[n + 2];
        float wx2 = fminf(br1x, b2.x) + fminf(ntl1x, b2.z);
        float wy2 = fminf(br1y, b2.y) + fminf(ntl1y, b2.w);
        float u2  = wx2 + fabsf(wx2);
        m2 = fmaxf(m2, fmaf(u2, wy2, s_th2[n + 2]));

        float4 b3 = s_box[n + 3];
        float wx3 = fminf(br1x, b3.x) + fminf(ntl1x, b3.z);
        float wy3 = fminf(br1y, b3.y) + fminf(ntl1y, b3.w);
        float u3  = wx3 + fabsf(wx3);
        m3 = fmaxf(m3, fmaf(u3, wy3, s_th2[n + 3]));
    }
    float mall = fmaxf(fmaxf(m0, m1), fmaxf(m2, m3));
    float background = (mall >= area1 * (2.0f / 3.0f)) ? 0.0f : (1.0f - gcf);

    // ---- focal BCE conf loss ----
    float pcl = fminf(fmaxf(oc, BCE_EPSF), 1.0f - BCE_EPSF);
    float bce = -(gcf * __logf(pcl) + (1.0f - gcf) * __logf(1.0f - pcl));
    float d = gcf - oc;
    float focal = fabsf(gcf - 0.75f) * (d * d);
    float conf_loss = focal * (gcf + background) * bce;

    float loss = giou_loss + conf_loss;

    // ---- block reduction ----
    #pragma unroll
    for (int off = 16; off > 0; off >>= 1)
        loss += __shfl_down_sync(0xffffffffu, loss, off);

    int wid = threadIdx.x >> 5, lid = threadIdx.x & 31;
    if (lid == 0) s_red[wid] = loss;
    __syncthreads();

    // ---- global accumulate; last block writes output and resets ----
    if (threadIdx.x == 0) {
        float t = 0.0f;
        #pragma unroll
        for (int i = 0; i < 8; i++) t += s_red[i];
        atomicAdd(&g_acc, (double)t);
        __threadfence();
        unsigned int old = atomicAdd(&g_count, 1u);
        if (old == NBLOCKS - 1) {
            double v = atomicAdd(&g_acc, 0.0);   // coherent read
            out[0] = (float)(v * (double)inv_b);
            g_acc = 0.0;                          // reset for next replay
            g_count = 0u;
            __threadfence();
        }
    }
}

extern "C" void kernel_launch(void* const* d_in, const int* in_sizes, int n_in,
                              void* d_out, int out_size)
{
    const float* s_out = (const float*)d_in[0];
    const float* m_out = (const float*)d_in[1];
    const float* l_out = (const float*)d_in[2];
    const float* s_gt  = (const float*)d_in[3];
    const float* m_gt  = (const float*)d_in[4];
    const float* l_gt  = (const float*)d_in[5];
    const float* s_gc  = (const float*)d_in[6];
    const float* m_gc  = (const float*)d_in[7];
    const float* l_gc  = (const float*)d_in[8];

    const int B = in_sizes[6] / (NGT * 4);   // 16

    fused_loss_kernel<<<NBLOCKS, 256>>>(s_out, m_out, l_out,
                                        s_gt, m_gt, l_gt,
                                        s_gc, m_gc, l_gc,
                                        (float*)d_out, 1.0f / (float)B);
}

// round 9
// speedup vs baseline: 1.9722x; 1.4867x over previous
#include <cuda_runtime.h>

#define EPSF     1e-9f
#define BCE_EPSF 1e-7f
#define NGT      150
#define NGT_PAD  152
#define NBLOCKS  1008   // 768 (s) + 192 (m) + 48 (l) with 256 threads/block

__device__ double       g_acc;
__device__ unsigned int g_count;

__global__ void __launch_bounds__(256) fused_loss_kernel(
    const float* __restrict__ s_out, const float* __restrict__ m_out,
    const float* __restrict__ l_out,
    const float* __restrict__ s_gt,  const float* __restrict__ m_gt,
    const float* __restrict__ l_gt,
    const float* __restrict__ s_gc,  const float* __restrict__ m_gc,
    const float* __restrict__ l_gc,
    float* __restrict__ out, float inv_b)
{
    __shared__ float4 s_box[NGT_PAD];        // brx, bry, -tlx, -tly (tl pre-negated)
    __shared__ float4 s_a43[NGT_PAD / 4];    // -(area2+eps)*(2/3), 4 boxes per float4
    __shared__ float  s_red[8];

    // ---- map block -> (scale, batch, local block) ----
    const int bb = blockIdx.x;
    const float *out_t, *gt_t, *gc;
    int b, lb, apb;
    if (bb < 768) {             // s: 48 blocks/batch, 12288 anchors
        b = bb / 48; lb = bb - b * 48; apb = 12288;
        out_t = s_out; gt_t = s_gt; gc = s_gc;
    } else if (bb < 960) {      // m: 12 blocks/batch
        int r = bb - 768; b = r / 12; lb = r - b * 12; apb = 3072;
        out_t = m_out; gt_t = m_gt; gc = m_gc;
    } else {                    // l: 3 blocks/batch
        int r = bb - 960; b = r / 3; lb = r - b * 3; apb = 768;
        out_t = l_out; gt_t = l_gt; gc = l_gc;
    }

    // ---- stage gt boxes (tl negated; thresholds packed float4, scaled 2/3) ----
    gc += (size_t)b * NGT * 4;
    for (int n = threadIdx.x; n < NGT_PAD; n += 256) {
        float th;
        if (n < NGT) {
            float x = gc[n * 4 + 0], y = gc[n * 4 + 1];
            float w = gc[n * 4 + 2], h = gc[n * 4 + 3];
            float hw = 0.5f * w, hh = 0.5f * h;
            s_box[n] = make_float4(x + hw, y + hh, hw - x, hh - y);
            th = -(w * h + EPSF) * (2.0f / 3.0f);
        } else {
            s_box[n] = make_float4(0.0f, 0.0f, 0.0f, 0.0f);
            th = -1.0e38f;          // sentinel: never exceeds threshold
        }
        ((float*)s_a43)[n] = th;
    }
    __syncthreads();

    const int a = lb * 256 + threadIdx.x;          // always < apb
    const size_t base = ((size_t)b * apb + a) * 5;
    const float* p = out_t + base;
    const float* q = gt_t  + base;
    float ox = p[0], oy = p[1], ow = p[2], oh = p[3], oc = p[4];
    float gx = q[0], gy = q[1], gw = q[2], gh = q[3], gcf = q[4];

    float tl1x = ox - 0.5f * ow, tl1y = oy - 0.5f * oh;
    float br1x = ox + 0.5f * ow, br1y = oy + 0.5f * oh;
    float ntl1x = -tl1x, ntl1y = -tl1y;
    float area1 = ow * oh;

    // ---- DIoU vs paired gt ----
    float tl2x = gx - 0.5f * gw, tl2y = gy - 0.5f * gh;
    float br2x = gx + 0.5f * gw, br2y = gy + 0.5f * gh;
    float area2 = gw * gh;

    float iwx = fmaxf(fminf(br1x, br2x) - fmaxf(tl1x, tl2x), 0.0f);
    float iwy = fmaxf(fminf(br1y, br2y) - fmaxf(tl1y, tl2y), 0.0f);
    float inter = iwx * iwy;
    float iou = inter / (area1 + area2 - inter + EPSF);

    float dx = ox - gx, dy = oy - gy;
    float cd2 = dx * dx + dy * dy;
    float ex = fmaxf(br1x, br2x) - fminf(tl1x, tl2x);
    float ey = fmaxf(br1y, br2y) - fminf(tl1y, tl2y);
    float diou = iou - cd2 / (ex * ex + ey * ey + EPSF);

    float giou_loss = gcf * (2.0f - area2 * (1.0f / (512.0f * 512.0f))) * (1.0f - diou);

    // ---- background gate: any(iou vs gt_coords >= 0.5)?
    // iou>=0.5 <=> 3*inter >= a1+a2+eps <=> (wx+|wx|)*wy >= (2/3)*(a1+a2+eps)
    float m0 = -3.0e38f, m1 = -3.0e38f, m2 = -3.0e38f, m3 = -3.0e38f;
    #pragma unroll 2
    for (int n = 0; n < NGT_PAD; n += 4) {
        float4 th = s_a43[n >> 2];    // pre-negated, pre-scaled thresholds

        float4 b0 = s_box[n];
        float wx0 = fminf(br1x, b0.x) + fminf(ntl1x, b0.z);
        float wy0 = fminf(br1y, b0.y) + fminf(ntl1y, b0.w);
        float u0  = wx0 + fabsf(wx0);               // 2*max(wx0,0), fma pipe
        m0 = fmaxf(m0, fmaf(u0, wy0, th.x));

        float4 b1 = s_box[n + 1];
        float wx1 = fminf(br1x, b1.x) + fminf(ntl1x, b1.z);
        float wy1 = fminf(br1y, b1.y) + fminf(ntl1y, b1.w);
        float u1  = wx1 + fabsf(wx1);
        m1 = fmaxf(m1, fmaf(u1, wy1, th.y));

        float4 b2 = s_box[n + 2];
        float wx2 = fminf(br1x, b2.x) + fminf(ntl1x, b2.z);
        float wy2 = fminf(br1y, b2.y) + fminf(ntl1y, b2.w);
        float u2  = wx2 + fabsf(wx2);
        m2 = fmaxf(m2, fmaf(u2, wy2, th.z));

        float4 b3 = s_box[n + 3];
        float wx3 = fminf(br1x, b3.x) + fminf(ntl1x, b3.z);
        float wy3 = fminf(br1y, b3.y) + fminf(ntl1y, b3.w);
        float u3  = wx3 + fabsf(wx3);
        m3 = fmaxf(m3, fmaf(u3, wy3, th.w));
    }
    float mall = fmaxf(fmaxf(m0, m1), fmaxf(m2, m3));
    float background = (mall >= area1 * (2.0f / 3.0f)) ? 0.0f : (1.0f - gcf);

    // ---- focal BCE conf loss ----
    float pcl = fminf(fmaxf(oc, BCE_EPSF), 1.0f - BCE_EPSF);
    float bce = -(gcf * __logf(pcl) + (1.0f - gcf) * __logf(1.0f - pcl));
    float d = gcf - oc;
    float focal = fabsf(gcf - 0.75f) * (d * d);
    float conf_loss = focal * (gcf + background) * bce;

    float loss = giou_loss + conf_loss;

    // ---- block reduction ----
    #pragma unroll
    for (int off = 16; off > 0; off >>= 1)
        loss += __shfl_down_sync(0xffffffffu, loss, off);

    int wid = threadIdx.x >> 5, lid = threadIdx.x & 31;
    if (lid == 0) s_red[wid] = loss;
    __syncthreads();

    // ---- global accumulate; last block writes output and resets ----
    if (threadIdx.x == 0) {
        float t = 0.0f;
        #pragma unroll
        for (int i = 0; i < 8; i++) t += s_red[i];
        atomicAdd(&g_acc, (double)t);
        __threadfence();
        unsigned int old = atomicAdd(&g_count, 1u);
        if (old == NBLOCKS - 1) {
            double v = atomicAdd(&g_acc, 0.0);   // coherent read
            out[0] = (float)(v * (double)inv_b);
            g_acc = 0.0;                          // reset for next replay
            g_count = 0u;
            __threadfence();
        }
    }
}

extern "C" void kernel_launch(void* const* d_in, const int* in_sizes, int n_in,
                              void* d_out, int out_size)
{
    const float* s_out = (const float*)d_in[0];
    const float* m_out = (const float*)d_in[1];
    const float* l_out = (const float*)d_in[2];
    const float* s_gt  = (const float*)d_in[3];
    const float* m_gt  = (const float*)d_in[4];
    const float* l_gt  = (const float*)d_in[5];
    const float* s_gc  = (const float*)d_in[6];
    const float* m_gc  = (const float*)d_in[7];
    const float* l_gc  = (const float*)d_in[8];

    const int B = in_sizes[6] / (NGT * 4);   // 16

    fused_loss_kernel<<<NBLOCKS, 256>>>(s_out, m_out, l_out,
                                        s_gt, m_gt, l_gt,
                                        s_gc, m_gc, l_gc,
                                        (float*)d_out, 1.0f / (float)B);
}